// round 2
// baseline (speedup 1.0000x reference)
#include <cuda_runtime.h>
#include <cuda_bf16.h>

#define HH  2048
#define DD  1024
#define TT  4096
#define G3H 6144   // 3*HH

#define NB      148   // persistent blocks (<= SM count)
#define NW      28    // compute warps / outputs per block (148*28 = 4144 >= 4096)
#define THREADS (NW * 32)
#define SMEM_BYTES (NW * 2 * HH * 2)   // 28 warps * 2 rows * 2048 bf16 = 229376 B

// ---------------- device scratch (allocation-free rule: __device__ globals) ---
__device__ float g_xp[2][TT][G3H];                       // ~201 MB
__device__ __align__(16) __nv_bfloat16 g_hb[2][2 * HH];  // double-buffered bf16 h
__device__ float g_h32[2 * HH];                          // final fp32 h for head
__device__ unsigned int g_bar;
__device__ float g_fc1[256];

// ---------------- prep: reset barrier counter --------------------------------
__global__ void prep_kernel() {
    if (threadIdx.x == 0 && blockIdx.x == 0) g_bar = 0u;
}

// ---------------- xp GEMM: C[T,3H] = A[T,D] @ B[3H,D]^T + bias (fp32) -------
__global__ void xp_gemm(const float* __restrict__ x1, const float* __restrict__ x2,
                        const float* __restrict__ Wih1, const float* __restrict__ Wih2,
                        const float* __restrict__ bih1, const float* __restrict__ bih2) {
    const int gru = blockIdx.z;
    const float* __restrict__ A    = gru ? x2   : x1;
    const float* __restrict__ B    = gru ? Wih2 : Wih1;
    const float* __restrict__ bias = gru ? bih2 : bih1;
    float* C = &g_xp[gru][0][0];

    __shared__ float As[8][128];
    __shared__ float Bs[8][128];

    const int tid = threadIdx.x;
    const int bm = blockIdx.y * 128;
    const int bn = blockIdx.x * 128;
    const int lr = tid >> 1;
    const int lk = (tid & 1) * 4;
    const int ty = tid >> 4;
    const int tx = tid & 15;

    float acc[8][8];
#pragma unroll
    for (int i = 0; i < 8; i++)
#pragma unroll
        for (int j = 0; j < 8; j++) acc[i][j] = 0.0f;

    for (int k0 = 0; k0 < DD; k0 += 8) {
        float4 av = *(const float4*)(A + (long long)(bm + lr) * DD + k0 + lk);
        float4 bv = *(const float4*)(B + (long long)(bn + lr) * DD + k0 + lk);
        __syncthreads();
        As[lk + 0][lr] = av.x; As[lk + 1][lr] = av.y;
        As[lk + 2][lr] = av.z; As[lk + 3][lr] = av.w;
        Bs[lk + 0][lr] = bv.x; Bs[lk + 1][lr] = bv.y;
        Bs[lk + 2][lr] = bv.z; Bs[lk + 3][lr] = bv.w;
        __syncthreads();
#pragma unroll
        for (int k = 0; k < 8; k++) {
            float a[8], b[8];
            float4 a0 = *(const float4*)&As[k][ty * 8];
            float4 a1 = *(const float4*)&As[k][ty * 8 + 4];
            float4 b0 = *(const float4*)&Bs[k][tx * 8];
            float4 b1 = *(const float4*)&Bs[k][tx * 8 + 4];
            a[0]=a0.x; a[1]=a0.y; a[2]=a0.z; a[3]=a0.w;
            a[4]=a1.x; a[5]=a1.y; a[6]=a1.z; a[7]=a1.w;
            b[0]=b0.x; b[1]=b0.y; b[2]=b0.z; b[3]=b0.w;
            b[4]=b1.x; b[5]=b1.y; b[6]=b1.z; b[7]=b1.w;
#pragma unroll
            for (int i = 0; i < 8; i++)
#pragma unroll
                for (int j = 0; j < 8; j++) acc[i][j] += a[i] * b[j];
        }
    }
#pragma unroll
    for (int i = 0; i < 8; i++) {
        const int row = bm + ty * 8 + i;
#pragma unroll
        for (int j = 0; j < 8; j++) {
            const int col = bn + tx * 8 + j;
            C[(long long)row * G3H + col] = acc[i][j] + bias[col];
        }
    }
}

// ---------------- persistent GRU scan ----------------------------------------
__device__ __forceinline__ unsigned int pack2(float a, float b) {
    __nv_bfloat162 p = __floats2bfloat162_rn(a, b);   // .x = a (low), .y = b (high)
    return *reinterpret_cast<unsigned int*>(&p);
}

__device__ __forceinline__ void acc2(float& a, unsigned int w, float lo, float hi) {
    a = fmaf(__int_as_float((int)(w << 16)), lo, a);
    a = fmaf(__int_as_float((int)(w & 0xffff0000u)), hi, a);
}

__device__ __forceinline__ void grid_bar(unsigned int target) {
    __syncthreads();
    if (threadIdx.x == 0) {
        __threadfence();
        atomicAdd(&g_bar, 1u);
        while (atomicAdd(&g_bar, 0u) < target) __nanosleep(64);
    }
    __syncthreads();
}

__global__ __launch_bounds__(THREADS, 1)
void gru_scan(const float* __restrict__ Whh1, const float* __restrict__ Whh2,
              const float* __restrict__ bhh1, const float* __restrict__ bhh2) {
    extern __shared__ uint4 smem[];
    const int tid  = threadIdx.x;
    const int wid  = tid >> 5;
    const int lane = tid & 31;
    const int o    = blockIdx.x * NW + wid;         // output element id
    const bool active = (o < 2 * HH);
    const int oc   = active ? o : 0;                // clamped for safe addressing
    const int gru  = oc >> 11;
    const int i    = oc & (HH - 1);

    uint4* s_r = smem + wid * 512;                  // 256 uint4 per row
    uint4* s_z = s_r + 256;

    unsigned int wn[32];                            // n-gate row, bf16x2 packed
    float br = 0.f, bz = 0.f, bnn = 0.f;

    if (active) {
        const float* __restrict__ W  = gru ? Whh2 : Whh1;
        const float* __restrict__ bh = gru ? bhh2 : bhh1;
        const float* r0 = W + (size_t)i * HH;
        const float* r1 = W + (size_t)(i + HH) * HH;
        const float* r2 = W + (size_t)(i + 2 * HH) * HH;
#pragma unroll
        for (int c = 0; c < 8; c++) {
            const int idx = c * 32 + lane;
            const int e   = idx * 8;
            float4 a0 = *(const float4*)(r0 + e);
            float4 a1 = *(const float4*)(r0 + e + 4);
            uint4 p;
            p.x = pack2(a0.x, a0.y); p.y = pack2(a0.z, a0.w);
            p.z = pack2(a1.x, a1.y); p.w = pack2(a1.z, a1.w);
            s_r[idx] = p;
            float4 b0 = *(const float4*)(r1 + e);
            float4 b1 = *(const float4*)(r1 + e + 4);
            p.x = pack2(b0.x, b0.y); p.y = pack2(b0.z, b0.w);
            p.z = pack2(b1.x, b1.y); p.w = pack2(b1.z, b1.w);
            s_z[idx] = p;
            float4 c0 = *(const float4*)(r2 + e);
            float4 c1 = *(const float4*)(r2 + e + 4);
            wn[c * 4 + 0] = pack2(c0.x, c0.y);
            wn[c * 4 + 1] = pack2(c0.z, c0.w);
            wn[c * 4 + 2] = pack2(c1.x, c1.y);
            wn[c * 4 + 3] = pack2(c1.z, c1.w);
        }
        if (lane == 0) {
            br  = bh[i];
            bz  = bh[i + HH];
            bnn = bh[i + 2 * HH];
            g_hb[0][o] = __float2bfloat16(0.0f);    // zero initial h (buffer 0)
        }
    }
    float h_own = 0.0f;

    grid_bar(NB * 1u);                              // weights + h0 visible everywhere

    const float* __restrict__ xpg = &g_xp[gru][0][0];

    for (int t = 0; t < TT; t++) {
        float ar = 0.f, az = 0.f, an = 0.f;
        if (active) {
            const uint4* __restrict__ hb = (const uint4*)(g_hb[t & 1] + gru * HH);
#pragma unroll
            for (int c = 0; c < 8; c++) {
                const int idx = c * 32 + lane;
                uint4 hv = __ldcg(hb + idx);
                uint4 rv = s_r[idx];
                uint4 zv = s_z[idx];
                {   float hl = __int_as_float((int)(hv.x << 16));
                    float hh = __int_as_float((int)(hv.x & 0xffff0000u));
                    acc2(ar, rv.x, hl, hh); acc2(az, zv.x, hl, hh); acc2(an, wn[c*4+0], hl, hh); }
                {   float hl = __int_as_float((int)(hv.y << 16));
                    float hh = __int_as_float((int)(hv.y & 0xffff0000u));
                    acc2(ar, rv.y, hl, hh); acc2(az, zv.y, hl, hh); acc2(an, wn[c*4+1], hl, hh); }
                {   float hl = __int_as_float((int)(hv.z << 16));
                    float hh = __int_as_float((int)(hv.z & 0xffff0000u));
                    acc2(ar, rv.z, hl, hh); acc2(az, zv.z, hl, hh); acc2(an, wn[c*4+2], hl, hh); }
                {   float hl = __int_as_float((int)(hv.w << 16));
                    float hh = __int_as_float((int)(hv.w & 0xffff0000u));
                    acc2(ar, rv.w, hl, hh); acc2(az, zv.w, hl, hh); acc2(an, wn[c*4+3], hl, hh); }
            }
#pragma unroll
            for (int off = 16; off; off >>= 1) {
                ar += __shfl_down_sync(0xffffffffu, ar, off);
                az += __shfl_down_sync(0xffffffffu, az, off);
                an += __shfl_down_sync(0xffffffffu, an, off);
            }
            if (lane == 0) {
                const float* __restrict__ xp = xpg + (size_t)t * G3H;
                const float r = 1.f / (1.f + expf(-(xp[i]           + ar + br)));
                const float z = 1.f / (1.f + expf(-(xp[i + HH]      + az + bz)));
                const float n = tanhf(        xp[i + 2 * HH] + bnn + an * r + (ar*0.f) );
                // NOTE: reference is tanh(xn + r*hn) with hn = an + bnn:
                const float n2 = tanhf(xp[i + 2 * HH] + r * (an + bnn));
                (void)n;
                h_own = (1.f - z) * n2 + z * h_own;
                g_hb[(t + 1) & 1][o] = __float2bfloat16(h_own);
            }
        }
        grid_bar((unsigned int)NB * (unsigned int)(t + 2));
    }

    if (active && lane == 0) g_h32[o] = h_own;
}

// ---------------- head: fc1 (relu) -------------------------------------------
__global__ void head_fc1(const float* __restrict__ w, const float* __restrict__ b) {
    __shared__ float red[256];
    const int row = blockIdx.x, tid = threadIdx.x;
    const float* __restrict__ wr = w + (long long)row * (2 * HH);
    float s = 0.f;
    for (int j = tid; j < 2 * HH; j += 256) s += wr[j] * g_h32[j];
    red[tid] = s; __syncthreads();
    for (int o = 128; o; o >>= 1) { if (tid < o) red[tid] += red[tid + o]; __syncthreads(); }
    if (tid == 0) { const float v = red[0] + b[row]; g_fc1[row] = v > 0.f ? v : 0.f; }
}

// ---------------- head: fc2 + log_softmax ------------------------------------
__global__ void head_fc2(const float* __restrict__ w, const float* __restrict__ b,
                         float* __restrict__ out) {
    __shared__ float logits[3];
    const int tid = threadIdx.x;
    const int wr = tid >> 5, lane = tid & 31;
    float s = 0.f;
    for (int j = lane; j < 256; j += 32) s += w[wr * 256 + j] * g_fc1[j];
#pragma unroll
    for (int off = 16; off; off >>= 1) s += __shfl_down_sync(0xffffffffu, s, off);
    if (lane == 0) logits[wr] = s + b[wr];
    __syncthreads();
    if (tid == 0) {
        const float m = fmaxf(logits[0], fmaxf(logits[1], logits[2]));
        const float l = logf(expf(logits[0] - m) + expf(logits[1] - m) + expf(logits[2] - m));
        out[0] = logits[0] - m - l;
        out[1] = logits[1] - m - l;
        out[2] = logits[2] - m - l;
    }
}

// ---------------- launcher ----------------------------------------------------
extern "C" void kernel_launch(void* const* d_in, const int* in_sizes, int n_in,
                              void* d_out, int out_size) {
    const float* x1    = (const float*)d_in[0];
    const float* x2    = (const float*)d_in[1];
    const float* W_ih1 = (const float*)d_in[2];
    const float* W_hh1 = (const float*)d_in[3];
    const float* b_ih1 = (const float*)d_in[4];
    const float* b_hh1 = (const float*)d_in[5];
    const float* W_ih2 = (const float*)d_in[6];
    const float* W_hh2 = (const float*)d_in[7];
    const float* b_ih2 = (const float*)d_in[8];
    const float* b_hh2 = (const float*)d_in[9];
    const float* fc1_w = (const float*)d_in[10];
    const float* fc1_b = (const float*)d_in[11];
    const float* fc2_w = (const float*)d_in[12];
    const float* fc2_b = (const float*)d_in[13];
    float* out = (float*)d_out;

    static bool attr_done = false;
    if (!attr_done) {
        cudaFuncSetAttribute(gru_scan, cudaFuncAttributeMaxDynamicSharedMemorySize, SMEM_BYTES);
        attr_done = true;
    }

    prep_kernel<<<1, 32>>>();
    xp_gemm<<<dim3(G3H / 128, TT / 128, 2), 256>>>(x1, x2, W_ih1, W_ih2, b_ih1, b_ih2);
    gru_scan<<<NB, THREADS, SMEM_BYTES>>>(W_hh1, W_hh2, b_hh1, b_hh2);
    head_fc1<<<256, 256>>>(fc1_w, fc1_b);
    head_fc2<<<1, 96>>>(fc2_w, fc2_b, out);
}

// round 3
// speedup vs baseline: 1.4880x; 1.4880x over previous
#include <cuda_runtime.h>
#include <cuda_bf16.h>

#define HH  2048
#define DD  1024
#define TT  4096
#define G3H 6144   // 3*HH

#define NB      148            // persistent blocks (<= SM count; GB300 has 152, B300 148)
#define NW      28             // warps per block; 148*28 = 4144 >= 4096 outputs
#define THREADS (NW * 32)

// ---------------- device scratch (allocation-free rule: __device__ globals) ---
__device__ float g_xp[2][TT][G3H];              // ~201 MB precomputed input projections
__device__ char  g_wq[2][G3H][HH];              // 25 MB int8 quantized W_hh
__device__ float g_wdq[2][G3H];                 // per-row dequant factor = max/ (127*127)
__device__ char  g_hq[2][2 * HH];               // double-buffered int8 h (scale 1/127)
__device__ float g_h32[2 * HH];                 // final fp32 h for the head
__device__ unsigned int g_bar;
__device__ float g_fc1[256];

// ---------------- prep: reset barrier, zero h0 -------------------------------
__global__ void prep_kernel() {
    if (blockIdx.x == 0) {
        if (threadIdx.x == 0) g_bar = 0u;
        for (int j = threadIdx.x; j < HH; j += blockDim.x)   // 2*HH bytes = HH/2 u32... zero 4KB
            ((unsigned int*)g_hq[0])[j & 1023] = 0u;
        // simpler full zero of buffer 0 (1024 words)
        for (int j = threadIdx.x; j < 1024; j += blockDim.x)
            ((unsigned int*)g_hq[0])[j] = 0u;
    }
}

// ---------------- quantize W_hh rows to int8 ---------------------------------
__global__ void quant_kernel(const float* __restrict__ W1, const float* __restrict__ W2) {
    const int bi  = blockIdx.x;            // 0..12287
    const int gru = bi / G3H;
    const int row = bi % G3H;
    const float* __restrict__ src = (gru ? W2 : W1) + (size_t)row * HH;
    __shared__ float red[256];
    const int tid = threadIdx.x;

    float m = 0.f;
    for (int j = tid; j < HH; j += 256) m = fmaxf(m, fabsf(src[j]));
    red[tid] = m; __syncthreads();
    for (int o = 128; o; o >>= 1) { if (tid < o) red[tid] = fmaxf(red[tid], red[tid + o]); __syncthreads(); }
    m = red[0];
    const float inv = (m > 0.f) ? 127.f / m : 0.f;
    if (tid == 0) g_wdq[gru][row] = m / (127.f * 127.f);

    // each thread quantizes 8 consecutive elements -> 2 packed u32 stores
    unsigned int* dst = (unsigned int*)&g_wq[gru][row][0];
#pragma unroll
    for (int v = 0; v < 2; v++) {
        const int e = tid * 8 + v * 4;
        unsigned int p = 0;
#pragma unroll
        for (int b = 0; b < 4; b++) {
            int q = __float2int_rn(src[e + b] * inv);
            q = max(-127, min(127, q));
            p |= ((unsigned int)(q & 0xff)) << (b * 8);
        }
        dst[e / 4] = p;
    }
}

// ---------------- xp GEMM: C[T,3H] = A[T,D] @ B[3H,D]^T + bias (fp32) -------
__global__ void xp_gemm(const float* __restrict__ x1, const float* __restrict__ x2,
                        const float* __restrict__ Wih1, const float* __restrict__ Wih2,
                        const float* __restrict__ bih1, const float* __restrict__ bih2) {
    const int gru = blockIdx.z;
    const float* __restrict__ A    = gru ? x2   : x1;
    const float* __restrict__ B    = gru ? Wih2 : Wih1;
    const float* __restrict__ bias = gru ? bih2 : bih1;
    float* C = &g_xp[gru][0][0];

    __shared__ float As[8][128];
    __shared__ float Bs[8][128];

    const int tid = threadIdx.x;
    const int bm = blockIdx.y * 128;
    const int bn = blockIdx.x * 128;
    const int lr = tid >> 1;
    const int lk = (tid & 1) * 4;
    const int ty = tid >> 4;
    const int tx = tid & 15;

    float acc[8][8];
#pragma unroll
    for (int i = 0; i < 8; i++)
#pragma unroll
        for (int j = 0; j < 8; j++) acc[i][j] = 0.0f;

    for (int k0 = 0; k0 < DD; k0 += 8) {
        float4 av = *(const float4*)(A + (long long)(bm + lr) * DD + k0 + lk);
        float4 bv = *(const float4*)(B + (long long)(bn + lr) * DD + k0 + lk);
        __syncthreads();
        As[lk + 0][lr] = av.x; As[lk + 1][lr] = av.y;
        As[lk + 2][lr] = av.z; As[lk + 3][lr] = av.w;
        Bs[lk + 0][lr] = bv.x; Bs[lk + 1][lr] = bv.y;
        Bs[lk + 2][lr] = bv.z; Bs[lk + 3][lr] = bv.w;
        __syncthreads();
#pragma unroll
        for (int k = 0; k < 8; k++) {
            float a[8], b[8];
            float4 a0 = *(const float4*)&As[k][ty * 8];
            float4 a1 = *(const float4*)&As[k][ty * 8 + 4];
            float4 b0 = *(const float4*)&Bs[k][tx * 8];
            float4 b1 = *(const float4*)&Bs[k][tx * 8 + 4];
            a[0]=a0.x; a[1]=a0.y; a[2]=a0.z; a[3]=a0.w;
            a[4]=a1.x; a[5]=a1.y; a[6]=a1.z; a[7]=a1.w;
            b[0]=b0.x; b[1]=b0.y; b[2]=b0.z; b[3]=b0.w;
            b[4]=b1.x; b[5]=b1.y; b[6]=b1.z; b[7]=b1.w;
#pragma unroll
            for (int i = 0; i < 8; i++)
#pragma unroll
                for (int j = 0; j < 8; j++) acc[i][j] += a[i] * b[j];
        }
    }
#pragma unroll
    for (int i = 0; i < 8; i++) {
        const int row = bm + ty * 8 + i;
#pragma unroll
        for (int j = 0; j < 8; j++) {
            const int col = bn + tx * 8 + j;
            C[(long long)row * G3H + col] = acc[i][j] + bias[col];
        }
    }
}

// ---------------- persistent GRU scan (int8 / DP4A) --------------------------
__global__ __launch_bounds__(THREADS, 1)
void gru_scan(const float* __restrict__ bhh1, const float* __restrict__ bhh2) {
    __shared__ uint4        s_r[NW * 128];      // r-gate rows, int8-packed: 56 KB
    __shared__ unsigned int s_h[1024];          // both GRUs' int8 h: 4 KB

    const int tid  = threadIdx.x;
    const int wid  = tid >> 5;
    const int lane = tid & 31;
    const int o    = blockIdx.x * NW + wid;
    const bool active = (o < 2 * HH);
    const int oc   = active ? o : 0;
    const int gru  = oc >> 11;
    const int i    = oc & (HH - 1);

    // ---- load weights: r row -> SMEM, z & n rows -> registers ----
    uint4 zr[4], nr[4];
    float fr = 0.f, fz = 0.f, fn = 0.f, br = 0.f, bz = 0.f, bnn = 0.f;
    {
        const uint4* r_row = (const uint4*)&g_wq[gru][i][0];
        const uint4* z_row = (const uint4*)&g_wq[gru][i + HH][0];
        const uint4* n_row = (const uint4*)&g_wq[gru][i + 2 * HH][0];
#pragma unroll
        for (int c = 0; c < 4; c++) {
            s_r[wid * 128 + c * 32 + lane] = r_row[c * 32 + lane];
            zr[c] = z_row[c * 32 + lane];
            nr[c] = n_row[c * 32 + lane];
        }
        fr  = g_wdq[gru][i];
        fz  = g_wdq[gru][i + HH];
        fn  = g_wdq[gru][i + 2 * HH];
        const float* __restrict__ bh = gru ? bhh2 : bhh1;
        br  = bh[i];
        bz  = bh[i + HH];
        bnn = bh[i + 2 * HH];
    }
    float h_own = 0.0f;
    const float* __restrict__ xpg = &g_xp[gru][0][0] ;
    unsigned int bar_target = 0;

    for (int t = 0; t < TT; t++) {
        // ---- stage h (int8, both GRUs) into SMEM ----
        {
            const unsigned int* __restrict__ hq = (const unsigned int*)g_hq[t & 1];
            if (tid < 1024) s_h[tid] = __ldcg(hq + tid);
            if (tid + THREADS < 1024) s_h[tid + THREADS] = __ldcg(hq + tid + THREADS);
        }
        __syncthreads();

        // ---- prefetch xp on lane 0 (hides DRAM latency under the dot) ----
        float xr = 0.f, xz = 0.f, xn = 0.f;
        if (active && lane == 0) {
            const float* __restrict__ xp = xpg + (size_t)t * G3H;
            xr = __ldg(xp + i);
            xz = __ldg(xp + i + HH);
            xn = __ldg(xp + i + 2 * HH);
        }

        int accr = 0, accz = 0, accn = 0;
        if (active) {
            const uint4* sh = (const uint4*)s_h + gru * 32;   // 32 uint4 per gru? (128 per gru)
            const uint4* sr = &s_r[wid * 128];
#pragma unroll
            for (int c = 0; c < 4; c++) {
                uint4 h4 = ((const uint4*)s_h)[gru * 128 + c * 32 + lane];
                uint4 r4 = sr[c * 32 + lane];
                accr = __dp4a((int)r4.x, (int)h4.x, accr);
                accr = __dp4a((int)r4.y, (int)h4.y, accr);
                accr = __dp4a((int)r4.z, (int)h4.z, accr);
                accr = __dp4a((int)r4.w, (int)h4.w, accr);
                accz = __dp4a((int)zr[c].x, (int)h4.x, accz);
                accz = __dp4a((int)zr[c].y, (int)h4.y, accz);
                accz = __dp4a((int)zr[c].z, (int)h4.z, accz);
                accz = __dp4a((int)zr[c].w, (int)h4.w, accz);
                accn = __dp4a((int)nr[c].x, (int)h4.x, accn);
                accn = __dp4a((int)nr[c].y, (int)h4.y, accn);
                accn = __dp4a((int)nr[c].z, (int)h4.z, accn);
                accn = __dp4a((int)nr[c].w, (int)h4.w, accn);
            }
            (void)sh;
#pragma unroll
            for (int off = 16; off; off >>= 1) {
                accr += __shfl_down_sync(0xffffffffu, accr, off);
                accz += __shfl_down_sync(0xffffffffu, accz, off);
                accn += __shfl_down_sync(0xffffffffu, accn, off);
            }
            if (lane == 0) {
                const float hr = (float)accr * fr + br;
                const float hz = (float)accz * fz + bz;
                const float hn = (float)accn * fn + bnn;
                const float r = 1.f / (1.f + expf(-(xr + hr)));
                const float z = 1.f / (1.f + expf(-(xz + hz)));
                const float n = tanhf(xn + r * hn);
                h_own = (1.f - z) * n + z * h_own;
                int q = __float2int_rn(h_own * 127.f);
                q = max(-127, min(127, q));
                g_hq[(t + 1) & 1][o] = (char)q;
            }
        }

        // ---- grid barrier ----
        bar_target += NB;
        __syncthreads();
        if (tid == 0) {
            __threadfence();
            atomicAdd(&g_bar, 1u);
            while (atomicAdd(&g_bar, 0u) < bar_target) __nanosleep(64);
            __threadfence();
        }
        __syncthreads();
    }

    if (active && lane == 0) g_h32[o] = h_own;
}

// ---------------- head: fc1 (relu) -------------------------------------------
__global__ void head_fc1(const float* __restrict__ w, const float* __restrict__ b) {
    __shared__ float red[256];
    const int row = blockIdx.x, tid = threadIdx.x;
    const float* __restrict__ wr = w + (long long)row * (2 * HH);
    float s = 0.f;
    for (int j = tid; j < 2 * HH; j += 256) s += wr[j] * g_h32[j];
    red[tid] = s; __syncthreads();
    for (int o = 128; o; o >>= 1) { if (tid < o) red[tid] += red[tid + o]; __syncthreads(); }
    if (tid == 0) { const float v = red[0] + b[row]; g_fc1[row] = v > 0.f ? v : 0.f; }
}

// ---------------- head: fc2 + log_softmax ------------------------------------
__global__ void head_fc2(const float* __restrict__ w, const float* __restrict__ b,
                         float* __restrict__ out) {
    __shared__ float logits[3];
    const int tid = threadIdx.x;
    const int wr = tid >> 5, lane = tid & 31;
    float s = 0.f;
    for (int j = lane; j < 256; j += 32) s += w[wr * 256 + j] * g_fc1[j];
#pragma unroll
    for (int off = 16; off; off >>= 1) s += __shfl_down_sync(0xffffffffu, s, off);
    if (lane == 0) logits[wr] = s + b[wr];
    __syncthreads();
    if (tid == 0) {
        const float m = fmaxf(logits[0], fmaxf(logits[1], logits[2]));
        const float l = logf(expf(logits[0] - m) + expf(logits[1] - m) + expf(logits[2] - m));
        out[0] = logits[0] - m - l;
        out[1] = logits[1] - m - l;
        out[2] = logits[2] - m - l;
    }
}

// ---------------- launcher ----------------------------------------------------
extern "C" void kernel_launch(void* const* d_in, const int* in_sizes, int n_in,
                              void* d_out, int out_size) {
    const float* x1    = (const float*)d_in[0];
    const float* x2    = (const float*)d_in[1];
    const float* W_ih1 = (const float*)d_in[2];
    const float* W_hh1 = (const float*)d_in[3];
    const float* b_ih1 = (const float*)d_in[4];
    const float* b_hh1 = (const float*)d_in[5];
    const float* W_ih2 = (const float*)d_in[6];
    const float* W_hh2 = (const float*)d_in[7];
    const float* b_ih2 = (const float*)d_in[8];
    const float* b_hh2 = (const float*)d_in[9];
    const float* fc1_w = (const float*)d_in[10];
    const float* fc1_b = (const float*)d_in[11];
    const float* fc2_w = (const float*)d_in[12];
    const float* fc2_b = (const float*)d_in[13];
    float* out = (float*)d_out;

    prep_kernel<<<1, 256>>>();
    quant_kernel<<<2 * G3H, 256>>>(W_hh1, W_hh2);
    xp_gemm<<<dim3(G3H / 128, TT / 128, 2), 256>>>(x1, x2, W_ih1, W_ih2, b_ih1, b_ih2);
    gru_scan<<<NB, THREADS>>>(b_hh1, b_hh2);
    head_fc1<<<256, 256>>>(fc1_w, fc1_b);
    head_fc2<<<1, 96>>>(fc2_w, fc2_b, out);
}

// round 4
// speedup vs baseline: 2.8218x; 1.8964x over previous
#include <cuda_runtime.h>
#include <cuda_bf16.h>

#define HH  2048
#define DD  1024
#define TT  4096
#define G3H 6144   // 3*HH

#define NB      148            // persistent blocks
#define GB      74             // blocks per barrier group (one group per GRU)
#define NW      28             // warps per block; 74*28 = 2072 >= 2048 outputs per GRU
#define THREADS (NW * 32)

// ---------------- device scratch (allocation-free rule: __device__ globals) ---
__device__ float g_xp[2][TT][G3H];              // ~201 MB precomputed input projections
__device__ char  g_wq[2][G3H][HH];              // 25 MB int8 quantized W_hh
__device__ float g_wdq[2][G3H];                 // per-row dequant factor = max/(127*127)
__device__ __align__(16) char g_hq[2][2][HH];   // [buffer][gru][H] int8 h (scale 1/127)
__device__ float g_h32[2 * HH];                 // final fp32 h for the head
__device__ unsigned int g_bar2[2];              // per-group monotonic arrival counters
__device__ float g_fc1[256];

// ---------------- prep: reset barriers, zero h0 ------------------------------
__global__ void prep_kernel() {
    if (threadIdx.x < 2) g_bar2[threadIdx.x] = 0u;
    for (int j = threadIdx.x; j < 1024; j += blockDim.x)
        ((unsigned int*)g_hq[0])[j] = 0u;       // zero buffer 0 (both GRUs)
}

// ---------------- quantize W_hh rows to int8 ---------------------------------
__global__ void quant_kernel(const float* __restrict__ W1, const float* __restrict__ W2) {
    const int bi  = blockIdx.x;            // 0..12287
    const int gru = bi / G3H;
    const int row = bi % G3H;
    const float* __restrict__ src = (gru ? W2 : W1) + (size_t)row * HH;
    __shared__ float red[256];
    const int tid = threadIdx.x;

    float m = 0.f;
    for (int j = tid; j < HH; j += 256) m = fmaxf(m, fabsf(src[j]));
    red[tid] = m; __syncthreads();
    for (int o = 128; o; o >>= 1) { if (tid < o) red[tid] = fmaxf(red[tid], red[tid + o]); __syncthreads(); }
    m = red[0];
    const float inv = (m > 0.f) ? 127.f / m : 0.f;
    if (tid == 0) g_wdq[gru][row] = m / (127.f * 127.f);

    unsigned int* dst = (unsigned int*)&g_wq[gru][row][0];
#pragma unroll
    for (int v = 0; v < 2; v++) {
        const int e = tid * 8 + v * 4;
        unsigned int p = 0;
#pragma unroll
        for (int b = 0; b < 4; b++) {
            int q = __float2int_rn(src[e + b] * inv);
            q = max(-127, min(127, q));
            p |= ((unsigned int)(q & 0xff)) << (b * 8);
        }
        dst[e / 4] = p;
    }
}

// ---------------- xp GEMM: C[T,3H] = A[T,D] @ B[3H,D]^T + bias (fp32) -------
__global__ void xp_gemm(const float* __restrict__ x1, const float* __restrict__ x2,
                        const float* __restrict__ Wih1, const float* __restrict__ Wih2,
                        const float* __restrict__ bih1, const float* __restrict__ bih2) {
    const int gru = blockIdx.z;
    const float* __restrict__ A    = gru ? x2   : x1;
    const float* __restrict__ B    = gru ? Wih2 : Wih1;
    const float* __restrict__ bias = gru ? bih2 : bih1;
    float* C = &g_xp[gru][0][0];

    __shared__ float As[8][128];
    __shared__ float Bs[8][128];

    const int tid = threadIdx.x;
    const int bm = blockIdx.y * 128;
    const int bn = blockIdx.x * 128;
    const int lr = tid >> 1;
    const int lk = (tid & 1) * 4;
    const int ty = tid >> 4;
    const int tx = tid & 15;

    float acc[8][8];
#pragma unroll
    for (int i = 0; i < 8; i++)
#pragma unroll
        for (int j = 0; j < 8; j++) acc[i][j] = 0.0f;

    for (int k0 = 0; k0 < DD; k0 += 8) {
        float4 av = *(const float4*)(A + (long long)(bm + lr) * DD + k0 + lk);
        float4 bv = *(const float4*)(B + (long long)(bn + lr) * DD + k0 + lk);
        __syncthreads();
        As[lk + 0][lr] = av.x; As[lk + 1][lr] = av.y;
        As[lk + 2][lr] = av.z; As[lk + 3][lr] = av.w;
        Bs[lk + 0][lr] = bv.x; Bs[lk + 1][lr] = bv.y;
        Bs[lk + 2][lr] = bv.z; Bs[lk + 3][lr] = bv.w;
        __syncthreads();
#pragma unroll
        for (int k = 0; k < 8; k++) {
            float a[8], b[8];
            float4 a0 = *(const float4*)&As[k][ty * 8];
            float4 a1 = *(const float4*)&As[k][ty * 8 + 4];
            float4 b0 = *(const float4*)&Bs[k][tx * 8];
            float4 b1 = *(const float4*)&Bs[k][tx * 8 + 4];
            a[0]=a0.x; a[1]=a0.y; a[2]=a0.z; a[3]=a0.w;
            a[4]=a1.x; a[5]=a1.y; a[6]=a1.z; a[7]=a1.w;
            b[0]=b0.x; b[1]=b0.y; b[2]=b0.z; b[3]=b0.w;
            b[4]=b1.x; b[5]=b1.y; b[6]=b1.z; b[7]=b1.w;
#pragma unroll
            for (int i = 0; i < 8; i++)
#pragma unroll
                for (int j = 0; j < 8; j++) acc[i][j] += a[i] * b[j];
        }
    }
#pragma unroll
    for (int i = 0; i < 8; i++) {
        const int row = bm + ty * 8 + i;
#pragma unroll
        for (int j = 0; j < 8; j++) {
            const int col = bn + tx * 8 + j;
            C[(long long)row * G3H + col] = acc[i][j] + bias[col];
        }
    }
}

// ---------------- persistent GRU scan (int8 / DP4A, split barriers) ----------
__global__ __launch_bounds__(THREADS, 1)
void gru_scan(const float* __restrict__ bhh1, const float* __restrict__ bhh2) {
    __shared__ uint4 s_r[NW * 128];      // r-gate rows, int8-packed: 56 KB
    __shared__ uint4 s_h[128];           // this GRU's int8 h: 2 KB

    const int tid  = threadIdx.x;
    const int wid  = tid >> 5;
    const int lane = tid & 31;
    const int grp  = (blockIdx.x < GB) ? 0 : 1;          // barrier group == gru
    const int blk  = blockIdx.x - grp * GB;
    const int ol   = blk * NW + wid;                     // local output id 0..2071
    const bool active = (ol < HH);
    const int i    = active ? ol : 0;
    const int gru  = grp;

    // ---- load weights: r row -> SMEM, z & n rows -> registers ----
    uint4 zr[4], nr[4];
    float fr = 0.f, fz = 0.f, fn = 0.f, br = 0.f, bz = 0.f, bnn = 0.f;
    {
        const uint4* r_row = (const uint4*)&g_wq[gru][i][0];
        const uint4* z_row = (const uint4*)&g_wq[gru][i + HH][0];
        const uint4* n_row = (const uint4*)&g_wq[gru][i + 2 * HH][0];
#pragma unroll
        for (int c = 0; c < 4; c++) {
            s_r[wid * 128 + c * 32 + lane] = r_row[c * 32 + lane];
            zr[c] = z_row[c * 32 + lane];
            nr[c] = n_row[c * 32 + lane];
        }
        fr  = g_wdq[gru][i];
        fz  = g_wdq[gru][i + HH];
        fn  = g_wdq[gru][i + 2 * HH];
        const float* __restrict__ bh = gru ? bhh2 : bhh1;
        br  = bh[i];
        bz  = bh[i + HH];
        bnn = bh[i + 2 * HH];
    }
    float h_own = 0.0f;
    const float* __restrict__ xpg = &g_xp[gru][0][0];

    // preload xp[0]
    float xr = 0.f, xz = 0.f, xn = 0.f;
    if (active && lane == 0) {
        xr = __ldg(xpg + i);
        xz = __ldg(xpg + i + HH);
        xn = __ldg(xpg + i + 2 * HH);
    }

    for (int t = 0; t < TT; t++) {
        // ---- prefetch xp[t+1] (off the critical chain) ----
        float pxr = 0.f, pxz = 0.f, pxn = 0.f;
        if (active && lane == 0 && t + 1 < TT) {
            const float* __restrict__ xp = xpg + (size_t)(t + 1) * G3H;
            pxr = __ldg(xp + i);
            pxz = __ldg(xp + i + HH);
            pxn = __ldg(xp + i + 2 * HH);
        }

        // ---- stage this GRU's h (int8) into SMEM ----
        if (tid < 128)
            s_h[tid] = __ldcg((const uint4*)g_hq[t & 1][gru] + tid);
        __syncthreads();

        if (active) {
            int accr = 0, accz = 0, accn = 0;
            const uint4* sr = &s_r[wid * 128];
#pragma unroll
            for (int c = 0; c < 4; c++) {
                uint4 h4 = s_h[c * 32 + lane];
                uint4 r4 = sr[c * 32 + lane];
                accr = __dp4a((int)r4.x, (int)h4.x, accr);
                accr = __dp4a((int)r4.y, (int)h4.y, accr);
                accr = __dp4a((int)r4.z, (int)h4.z, accr);
                accr = __dp4a((int)r4.w, (int)h4.w, accr);
                accz = __dp4a((int)zr[c].x, (int)h4.x, accz);
                accz = __dp4a((int)zr[c].y, (int)h4.y, accz);
                accz = __dp4a((int)zr[c].z, (int)h4.z, accz);
                accz = __dp4a((int)zr[c].w, (int)h4.w, accz);
                accn = __dp4a((int)nr[c].x, (int)h4.x, accn);
                accn = __dp4a((int)nr[c].y, (int)h4.y, accn);
                accn = __dp4a((int)nr[c].z, (int)h4.z, accn);
                accn = __dp4a((int)nr[c].w, (int)h4.w, accn);
            }
#pragma unroll
            for (int off = 16; off; off >>= 1) {
                accr += __shfl_down_sync(0xffffffffu, accr, off);
                accz += __shfl_down_sync(0xffffffffu, accz, off);
                accn += __shfl_down_sync(0xffffffffu, accn, off);
            }
            if (lane == 0) {
                const float hr = (float)accr * fr + br;
                const float hz = (float)accz * fz + bz;
                const float hn = (float)accn * fn + bnn;
                const float r = 1.f / (1.f + expf(-(xr + hr)));
                const float z = 1.f / (1.f + expf(-(xz + hz)));
                const float n = tanhf(xn + r * hn);
                h_own = (1.f - z) * n + z * h_own;
                int q = __float2int_rn(h_own * 127.f);
                q = max(-127, min(127, q));
                g_hq[(t + 1) & 1][gru][i] = (char)q;
            }
        }

        // ---- group barrier: RED arrival + plain acquire-load poll ----
        __syncthreads();
        if (tid == 0) {
            __threadfence();
            asm volatile("red.release.gpu.global.add.u32 [%0], %1;"
                         :: "l"(&g_bar2[grp]), "r"(1u) : "memory");
            const unsigned int target = (unsigned int)GB * (unsigned int)(t + 1);
            unsigned int v;
            do {
                asm volatile("ld.acquire.gpu.global.u32 %0, [%1];"
                             : "=r"(v) : "l"(&g_bar2[grp]) : "memory");
            } while (v < target);
        }
        __syncthreads();

        xr = pxr; xz = pxz; xn = pxn;
    }

    if (active && lane == 0) g_h32[gru * HH + i] = h_own;
}

// ---------------- head: fc1 (relu) -------------------------------------------
__global__ void head_fc1(const float* __restrict__ w, const float* __restrict__ b) {
    __shared__ float red[256];
    const int row = blockIdx.x, tid = threadIdx.x;
    const float* __restrict__ wr = w + (long long)row * (2 * HH);
    float s = 0.f;
    for (int j = tid; j < 2 * HH; j += 256) s += wr[j] * g_h32[j];
    red[tid] = s; __syncthreads();
    for (int o = 128; o; o >>= 1) { if (tid < o) red[tid] += red[tid + o]; __syncthreads(); }
    if (tid == 0) { const float v = red[0] + b[row]; g_fc1[row] = v > 0.f ? v : 0.f; }
}

// ---------------- head: fc2 + log_softmax ------------------------------------
__global__ void head_fc2(const float* __restrict__ w, const float* __restrict__ b,
                         float* __restrict__ out) {
    __shared__ float logits[3];
    const int tid = threadIdx.x;
    const int wr = tid >> 5, lane = tid & 31;
    float s = 0.f;
    for (int j = lane; j < 256; j += 32) s += w[wr * 256 + j] * g_fc1[j];
#pragma unroll
    for (int off = 16; off; off >>= 1) s += __shfl_down_sync(0xffffffffu, s, off);
    if (lane == 0) logits[wr] = s + b[wr];
    __syncthreads();
    if (tid == 0) {
        const float m = fmaxf(logits[0], fmaxf(logits[1], logits[2]));
        const float l = logf(expf(logits[0] - m) + expf(logits[1] - m) + expf(logits[2] - m));
        out[0] = logits[0] - m - l;
        out[1] = logits[1] - m - l;
        out[2] = logits[2] - m - l;
    }
}

// ---------------- launcher ----------------------------------------------------
extern "C" void kernel_launch(void* const* d_in, const int* in_sizes, int n_in,
                              void* d_out, int out_size) {
    const float* x1    = (const float*)d_in[0];
    const float* x2    = (const float*)d_in[1];
    const float* W_ih1 = (const float*)d_in[2];
    const float* W_hh1 = (const float*)d_in[3];
    const float* b_ih1 = (const float*)d_in[4];
    const float* b_hh1 = (const float*)d_in[5];
    const float* W_ih2 = (const float*)d_in[6];
    const float* W_hh2 = (const float*)d_in[7];
    const float* b_ih2 = (const float*)d_in[8];
    const float* b_hh2 = (const float*)d_in[9];
    const float* fc1_w = (const float*)d_in[10];
    const float* fc1_b = (const float*)d_in[11];
    const float* fc2_w = (const float*)d_in[12];
    const float* fc2_b = (const float*)d_in[13];
    float* out = (float*)d_out;

    prep_kernel<<<1, 256>>>();
    quant_kernel<<<2 * G3H, 256>>>(W_hh1, W_hh2);
    xp_gemm<<<dim3(G3H / 128, TT / 128, 2), 256>>>(x1, x2, W_ih1, W_ih2, b_ih1, b_ih2);
    gru_scan<<<NB, THREADS>>>(b_hh1, b_hh2);
    head_fc1<<<256, 256>>>(fc1_w, fc1_b);
    head_fc2<<<1, 96>>>(fc2_w, fc2_b, out);
}

// round 6
// speedup vs baseline: 3.9336x; 1.3940x over previous
#include <cuda_runtime.h>
#include <cuda_bf16.h>

#define HH  2048
#define DD  1024
#define TT  4096
#define G3H 6144   // 3*HH

#define NB      148            // persistent blocks
#define GB      74             // blocks per barrier group (one group per GRU)
#define NW      28             // warps per block; 74*28 = 2072 >= 2048 outputs per GRU
#define THREADS (NW * 32)

// ---------------- device scratch (allocation-free rule: __device__ globals) ---
__device__ float g_xp[2][TT][G3H];                 // ~201 MB precomputed input projections
__device__ __nv_bfloat16 g_xb[2][TT][DD];          // 16.8 MB bf16 x
__device__ __nv_bfloat16 g_wb[2][G3H][DD];         // 25 MB bf16 W_ih
__device__ char  g_wq[2][G3H][HH];                 // 25 MB int8 quantized W_hh
__device__ float g_wdq[2][G3H];                    // per-row dequant factor
__device__ __align__(16) char g_hq[2][2][HH];      // [buffer][gru][H] int8 h (scale 1/127)
__device__ float g_h32[2 * HH];                    // final fp32 h for the head
__device__ unsigned int g_bar2[2];                 // per-group arrival counters
__device__ float g_fc1[256];

// ---------------- prep: reset barriers, zero h0 ------------------------------
__global__ void prep_kernel() {
    if (threadIdx.x < 2) g_bar2[threadIdx.x] = 0u;
    for (int j = threadIdx.x; j < 1024; j += blockDim.x)
        ((unsigned int*)g_hq[0])[j] = 0u;
}

// ---------------- convert x, W_ih to bf16 ------------------------------------
__global__ void conv_bf16(const float* __restrict__ x1, const float* __restrict__ x2,
                          const float* __restrict__ W1, const float* __restrict__ W2) {
    const long long idx    = (long long)blockIdx.x * blockDim.x + threadIdx.x;
    const long long stride = (long long)gridDim.x * blockDim.x;
    const long long NX = (long long)TT * DD;
    const long long NW_ = (long long)G3H * DD;
    for (long long i = idx; i < NX; i += stride) {
        ((__nv_bfloat16*)g_xb[0])[i] = __float2bfloat16(x1[i]);
        ((__nv_bfloat16*)g_xb[1])[i] = __float2bfloat16(x2[i]);
    }
    for (long long i = idx; i < NW_; i += stride) {
        ((__nv_bfloat16*)g_wb[0])[i] = __float2bfloat16(W1[i]);
        ((__nv_bfloat16*)g_wb[1])[i] = __float2bfloat16(W2[i]);
    }
}

// ---------------- quantize W_hh rows to int8 ---------------------------------
__global__ void quant_kernel(const float* __restrict__ W1, const float* __restrict__ W2) {
    const int bi  = blockIdx.x;
    const int gru = bi / G3H;
    const int row = bi % G3H;
    const float* __restrict__ src = (gru ? W2 : W1) + (size_t)row * HH;
    __shared__ float red[256];
    const int tid = threadIdx.x;

    float m = 0.f;
    for (int j = tid; j < HH; j += 256) m = fmaxf(m, fabsf(src[j]));
    red[tid] = m; __syncthreads();
    for (int o = 128; o; o >>= 1) { if (tid < o) red[tid] = fmaxf(red[tid], red[tid + o]); __syncthreads(); }
    m = red[0];
    const float inv = (m > 0.f) ? 127.f / m : 0.f;
    if (tid == 0) g_wdq[gru][row] = m / (127.f * 127.f);

    unsigned int* dst = (unsigned int*)&g_wq[gru][row][0];
#pragma unroll
    for (int v = 0; v < 2; v++) {
        const int e = tid * 8 + v * 4;
        unsigned int p = 0;
#pragma unroll
        for (int b = 0; b < 4; b++) {
            int q = __float2int_rn(src[e + b] * inv);
            q = max(-127, min(127, q));
            p |= ((unsigned int)(q & 0xff)) << (b * 8);
        }
        dst[e / 4] = p;
    }
}

// ---------------- xp GEMM via bf16 mma.sync ----------------------------------
// C[T,3H] = A[T,D] @ B[3H,D]^T + bias.  Block tile 128x128, k-slab 32, 8 warps.
__device__ __forceinline__ void ldsm4(unsigned int* r, const void* p) {
    unsigned int sa = (unsigned int)__cvta_generic_to_shared(p);
    asm volatile("ldmatrix.sync.aligned.m8n8.x4.shared.b16 {%0,%1,%2,%3}, [%4];"
                 : "=r"(r[0]), "=r"(r[1]), "=r"(r[2]), "=r"(r[3]) : "r"(sa));
}
__device__ __forceinline__ void mma16816(float* c, const unsigned int* a,
                                         unsigned int b0, unsigned int b1) {
    asm volatile("mma.sync.aligned.m16n8k16.row.col.f32.bf16.bf16.f32 "
                 "{%0,%1,%2,%3}, {%4,%5,%6,%7}, {%8,%9}, {%0,%1,%2,%3};"
                 : "+f"(c[0]), "+f"(c[1]), "+f"(c[2]), "+f"(c[3])
                 : "r"(a[0]), "r"(a[1]), "r"(a[2]), "r"(a[3]), "r"(b0), "r"(b1));
}

__global__ __launch_bounds__(256, 2)
void xp_gemm_mma(const float* __restrict__ bih1, const float* __restrict__ bih2) {
    __shared__ __nv_bfloat16 As[128][40];
    __shared__ __nv_bfloat16 Bs[128][40];

    const int gru = blockIdx.z;
    const int bm  = blockIdx.y * 128;     // T tile
    const int bn  = blockIdx.x * 128;     // 3H tile
    const __nv_bfloat16* __restrict__ Ag = &g_xb[gru][0][0];
    const __nv_bfloat16* __restrict__ Bg = &g_wb[gru][0][0];
    const float* __restrict__ bias = gru ? bih2 : bih1;

    const int tid  = threadIdx.x;
    const int warp = tid >> 5;
    const int lane = tid & 31;
    const int wm   = warp & 3;            // 0..3  -> m0 = wm*32
    const int wn   = warp >> 2;           // 0..1  -> n0 = wn*64

    float acc[2][8][4];
#pragma unroll
    for (int i = 0; i < 2; i++)
#pragma unroll
        for (int j = 0; j < 8; j++)
#pragma unroll
            for (int k = 0; k < 4; k++) acc[i][j][k] = 0.f;

    for (int k0 = 0; k0 < DD; k0 += 32) {
        // load A, B slabs (each 128 rows x 32 bf16)
#pragma unroll
        for (int v = 0; v < 2; v++) {
            const int e  = tid + v * 256;      // uint4 index, 0..511
            const int r  = e >> 2;
            const int cc = (e & 3) * 8;
            *(uint4*)&As[r][cc] = *(const uint4*)(Ag + (size_t)(bm + r) * DD + k0 + cc);
            *(uint4*)&Bs[r][cc] = *(const uint4*)(Bg + (size_t)(bn + r) * DD + k0 + cc);
        }
        __syncthreads();

#pragma unroll
        for (int kk = 0; kk < 32; kk += 16) {
            unsigned int a[2][4], b[4][4];
            const int arow = (lane & 15);
            const int acol = kk + 8 * (lane >> 4);
#pragma unroll
            for (int mf = 0; mf < 2; mf++)
                ldsm4(a[mf], &As[wm * 32 + mf * 16 + arow][acol]);
#pragma unroll
            for (int nb = 0; nb < 4; nb++)
                ldsm4(b[nb], &Bs[wn * 64 + nb * 16 + arow][acol]);
#pragma unroll
            for (int mf = 0; mf < 2; mf++)
#pragma unroll
                for (int nb = 0; nb < 4; nb++) {
                    mma16816(acc[mf][nb * 2 + 0], a[mf], b[nb][0], b[nb][2]);
                    mma16816(acc[mf][nb * 2 + 1], a[mf], b[nb][1], b[nb][3]);
                }
        }
        __syncthreads();
    }

    // epilogue: add bias, store fp32
    float* __restrict__ C = &g_xp[gru][0][0];
#pragma unroll
    for (int nf = 0; nf < 8; nf++) {
        const int gn = bn + wn * 64 + nf * 8 + (lane & 3) * 2;
        const float b0 = __ldg(bias + gn);
        const float b1 = __ldg(bias + gn + 1);
#pragma unroll
        for (int mf = 0; mf < 2; mf++) {
            const int gm = bm + wm * 32 + mf * 16 + (lane >> 2);
            C[(size_t)gm * G3H + gn]           = acc[mf][nf][0] + b0;
            C[(size_t)gm * G3H + gn + 1]       = acc[mf][nf][1] + b1;
            C[(size_t)(gm + 8) * G3H + gn]     = acc[mf][nf][2] + b0;
            C[(size_t)(gm + 8) * G3H + gn + 1] = acc[mf][nf][3] + b1;
        }
    }
}

// ---------------- persistent GRU scan (int8 / DP4A, split barriers) ----------
__global__ __launch_bounds__(THREADS, 1)
void gru_scan(const float* __restrict__ bhh1, const float* __restrict__ bhh2) {
    __shared__ uint4 s_r[NW * 128];      // r-gate rows, int8-packed: 56 KB
    __shared__ uint4 s_h[128];           // this GRU's int8 h: 2 KB

    const int tid  = threadIdx.x;
    const int wid  = tid >> 5;
    const int lane = tid & 31;
    const int grp  = (blockIdx.x < GB) ? 0 : 1;          // barrier group == gru
    const int blk  = blockIdx.x - grp * GB;
    const int ol   = blk * NW + wid;                     // local output id
    const bool active = (ol < HH);
    const int i    = active ? ol : 0;
    const int gru  = grp;

    uint4 zr[4], nr[4];
    float fr = 0.f, fz = 0.f, fn = 0.f, br = 0.f, bz = 0.f, bnn = 0.f;
    {
        const uint4* r_row = (const uint4*)&g_wq[gru][i][0];
        const uint4* z_row = (const uint4*)&g_wq[gru][i + HH][0];
        const uint4* n_row = (const uint4*)&g_wq[gru][i + 2 * HH][0];
#pragma unroll
        for (int c = 0; c < 4; c++) {
            s_r[wid * 128 + c * 32 + lane] = r_row[c * 32 + lane];
            zr[c] = z_row[c * 32 + lane];
            nr[c] = n_row[c * 32 + lane];
        }
        fr  = g_wdq[gru][i];
        fz  = g_wdq[gru][i + HH];
        fn  = g_wdq[gru][i + 2 * HH];
        const float* __restrict__ bh = gru ? bhh2 : bhh1;
        br  = bh[i];
        bz  = bh[i + HH];
        bnn = bh[i + 2 * HH];
    }
    float h_own = 0.0f;
    const float* __restrict__ xpg = &g_xp[gru][0][0];

    float xr = 0.f, xz = 0.f, xn = 0.f;
    if (active && lane == 0) {
        xr = __ldg(xpg + i);
        xz = __ldg(xpg + i + HH);
        xn = __ldg(xpg + i + 2 * HH);
    }

    for (int t = 0; t < TT; t++) {
        float pxr = 0.f, pxz = 0.f, pxn = 0.f;
        if (active && lane == 0 && t + 1 < TT) {
            const float* __restrict__ xp = xpg + (size_t)(t + 1) * G3H;
            pxr = __ldg(xp + i);
            pxz = __ldg(xp + i + HH);
            pxn = __ldg(xp + i + 2 * HH);
        }

        if (tid < 128)
            s_h[tid] = __ldcg((const uint4*)g_hq[t & 1][gru] + tid);
        __syncthreads();

        if (active) {
            int accr = 0, accz = 0, accn = 0;
            const uint4* sr = &s_r[wid * 128];
#pragma unroll
            for (int c = 0; c < 4; c++) {
                uint4 h4 = s_h[c * 32 + lane];
                uint4 r4 = sr[c * 32 + lane];
                accr = __dp4a((int)r4.x, (int)h4.x, accr);
                accr = __dp4a((int)r4.y, (int)h4.y, accr);
                accr = __dp4a((int)r4.z, (int)h4.z, accr);
                accr = __dp4a((int)r4.w, (int)h4.w, accr);
                accz = __dp4a((int)zr[c].x, (int)h4.x, accz);
                accz = __dp4a((int)zr[c].y, (int)h4.y, accz);
                accz = __dp4a((int)zr[c].z, (int)h4.z, accz);
                accz = __dp4a((int)zr[c].w, (int)h4.w, accz);
                accn = __dp4a((int)nr[c].x, (int)h4.x, accn);
                accn = __dp4a((int)nr[c].y, (int)h4.y, accn);
                accn = __dp4a((int)nr[c].z, (int)h4.z, accn);
                accn = __dp4a((int)nr[c].w, (int)h4.w, accn);
            }
            accr = __reduce_add_sync(0xffffffffu, accr);
            accz = __reduce_add_sync(0xffffffffu, accz);
            accn = __reduce_add_sync(0xffffffffu, accn);
            if (lane == 0) {
                const float hr = (float)accr * fr + br;
                const float hz = (float)accz * fz + bz;
                const float hn = (float)accn * fn + bnn;
                const float r = __fdividef(1.f, 1.f + __expf(-(xr + hr)));
                const float z = __fdividef(1.f, 1.f + __expf(-(xz + hz)));
                float n;
                asm("tanh.approx.f32 %0, %1;" : "=f"(n) : "f"(xn + r * hn));
                h_own = (1.f - z) * n + z * h_own;
                int q = __float2int_rn(h_own * 127.f);
                q = max(-127, min(127, q));
                g_hq[(t + 1) & 1][gru][i] = (char)q;
            }
        }

        // ---- group barrier: RED release arrival + acquire-load poll ----
        __syncthreads();
        if (tid == 0) {
            asm volatile("red.release.gpu.global.add.u32 [%0], %1;"
                         :: "l"(&g_bar2[grp]), "r"(1u) : "memory");
            const unsigned int target = (unsigned int)GB * (unsigned int)(t + 1);
            unsigned int v;
            do {
                asm volatile("ld.acquire.gpu.global.u32 %0, [%1];"
                             : "=r"(v) : "l"(&g_bar2[grp]) : "memory");
            } while (v < target);
        }
        __syncthreads();

        xr = pxr; xz = pxz; xn = pxn;
    }

    if (active && lane == 0) g_h32[gru * HH + i] = h_own;
}

// ---------------- head: fc1 (relu) -------------------------------------------
__global__ void head_fc1(const float* __restrict__ w, const float* __restrict__ b) {
    __shared__ float red[256];
    const int row = blockIdx.x, tid = threadIdx.x;
    const float* __restrict__ wr = w + (long long)row * (2 * HH);
    float s = 0.f;
    for (int j = tid; j < 2 * HH; j += 256) s += wr[j] * g_h32[j];
    red[tid] = s; __syncthreads();
    for (int o = 128; o; o >>= 1) { if (tid < o) red[tid] += red[tid + o]; __syncthreads(); }
    if (tid == 0) { const float v = red[0] + b[row]; g_fc1[row] = v > 0.f ? v : 0.f; }
}

// ---------------- head: fc2 + log_softmax ------------------------------------
__global__ void head_fc2(const float* __restrict__ w, const float* __restrict__ b,
                         float* __restrict__ out) {
    __shared__ float logits[3];
    const int tid = threadIdx.x;
    const int wr = tid >> 5, lane = tid & 31;
    float s = 0.f;
    for (int j = lane; j < 256; j += 32) s += w[wr * 256 + j] * g_fc1[j];
#pragma unroll
    for (int off = 16; off; off >>= 1) s += __shfl_down_sync(0xffffffffu, s, off);
    if (lane == 0) logits[wr] = s + b[wr];
    __syncthreads();
    if (tid == 0) {
        const float m = fmaxf(logits[0], fmaxf(logits[1], logits[2]));
        const float l = logf(expf(logits[0] - m) + expf(logits[1] - m) + expf(logits[2] - m));
        out[0] = logits[0] - m - l;
        out[1] = logits[1] - m - l;
        out[2] = logits[2] - m - l;
    }
}

// ---------------- launcher ----------------------------------------------------
extern "C" void kernel_launch(void* const* d_in, const int* in_sizes, int n_in,
                              void* d_out, int out_size) {
    const float* x1    = (const float*)d_in[0];
    const float* x2    = (const float*)d_in[1];
    const float* W_ih1 = (const float*)d_in[2];
    const float* W_hh1 = (const float*)d_in[3];
    const float* b_ih1 = (const float*)d_in[4];
    const float* b_hh1 = (const float*)d_in[5];
    const float* W_ih2 = (const float*)d_in[6];
    const float* W_hh2 = (const float*)d_in[7];
    const float* b_ih2 = (const float*)d_in[8];
    const float* b_hh2 = (const float*)d_in[9];
    const float* fc1_w = (const float*)d_in[10];
    const float* fc1_b = (const float*)d_in[11];
    const float* fc2_w = (const float*)d_in[12];
    const float* fc2_b = (const float*)d_in[13];
    float* out = (float*)d_out;

    prep_kernel<<<1, 256>>>();
    conv_bf16<<<1024, 256>>>(x1, x2, W_ih1, W_ih2);
    quant_kernel<<<2 * G3H, 256>>>(W_hh1, W_hh2);
    xp_gemm_mma<<<dim3(G3H / 128, TT / 128, 2), 256>>>(b_ih1, b_ih2);
    gru_scan<<<NB, THREADS>>>(b_hh1, b_hh2);
    head_fc1<<<256, 256>>>(fc1_w, fc1_b);
    head_fc2<<<1, 96>>>(fc2_w, fc2_b, out);
}